// round 4
// baseline (speedup 1.0000x reference)
#include <cuda_runtime.h>

typedef unsigned long long u64;

#define TT    64
#define BATCH 8192
#define DIN   128
#define BT    64
#define NCTA  (BATCH / BT)

#define G1 128
#define G2 64
#define G3 32
#define H1 32
#define H2 16
#define H3 8

// ---------------- phase A (XG = x @ W_ih1^T + b1) ----------------
#define TPB 8            // timesteps per phase-A block
#define NTA 256          // phase-A threads (8 warps -> 4/SMSP at 2 CTAs/SM)
#define WS_STRIDE 132    // padded [k][g] weight tile
#define XT_STRIDE 68     // padded [k][b] x tile
#define A_SMEM_FLOATS (DIN * WS_STRIDE + DIN * XT_STRIDE)
#define A_SMEM_BYTES  (A_SMEM_FLOATS * 4)

// ---------------- phase B (recurrent) ----------------
#define NTB 512
// smem float offsets
#define OFF_W1H 0        // [32k][128g]
#define OFF_W2X 4096     // [32k][64g]
#define OFF_W2H 6144     // [16k][64g]
#define OFF_B2  7168     // [64]
#define OFF_W3X 7232     // [16k][32g]
#define OFF_W3H 7744     // [8k][32g]
#define OFF_B3  8000     // [32]
#define OFF_GS  8032     // [128][64]
#define OFF_H1S 16224    // [32][64]
#define OFF_C1S 18272
#define OFF_H2S 20320    // [16][64]
#define OFF_C2S 21344
#define OFF_H3S 22368    // [8][64]
#define OFF_C3S 22880
#define B_SMEM_FLOATS 23392
#define B_SMEM_BYTES  (B_SMEM_FLOATS * 4)

// 256 MB scratch: XG[cta][t][g][bl]
__device__ float g_xg[(size_t)NCTA * TT * G1 * BT];

__device__ __forceinline__ u64 pack2(float a, float b) {
    u64 r;
    asm("mov.b64 %0, {%1, %2};" : "=l"(r) : "f"(a), "f"(b));
    return r;
}
__device__ __forceinline__ u64 fma2(u64 a, u64 b, u64 c) {
    u64 d;
    asm("fma.rn.f32x2 %0, %1, %2, %3;" : "=l"(d) : "l"(a), "l"(b), "l"(c));
    return d;
}
__device__ __forceinline__ float sigf(float v) {
    return __fdividef(1.f, 1.f + __expf(-v));
}
__device__ __forceinline__ float tanhf_(float v) {
    return 1.f - __fdividef(2.f, __expf(2.f * v) + 1.f);
}

// Generic MAC loop: acc[GPT gates][NBP batch-pairs] += W[k][g0..] * S[k][b0l..]
template <int WSTR, int SSTR, int GPT, int NBP, int K>
__device__ __forceinline__ void accum(const float* __restrict__ W,
                                      const float* __restrict__ S,
                                      u64 (&acc)[GPT][NBP], int g0, int b0l) {
#pragma unroll 2
    for (int k = 0; k < K; k++) {
        const float* wr = W + k * WSTR + g0;
        float wv[GPT];
        if constexpr (GPT == 8) {
            float4 a = *(const float4*)wr;
            float4 b = *(const float4*)(wr + 4);
            wv[0] = a.x; wv[1] = a.y; wv[2] = a.z; wv[3] = a.w;
            wv[4] = b.x; wv[5] = b.y; wv[6] = b.z; wv[7] = b.w;
        } else if constexpr (GPT == 4) {
            float4 a = *(const float4*)wr;
            wv[0] = a.x; wv[1] = a.y; wv[2] = a.z; wv[3] = a.w;
        } else {
            float2 a = *(const float2*)wr;
            wv[0] = a.x; wv[1] = a.y;
        }
        const float* sr = S + k * SSTR + b0l;
        u64 xp[NBP];
        if constexpr (NBP == 4) {
            ulonglong2 a = *(const ulonglong2*)sr;
            ulonglong2 b = *(const ulonglong2*)(sr + 4);
            xp[0] = a.x; xp[1] = a.y; xp[2] = b.x; xp[3] = b.y;
        } else if constexpr (NBP == 2) {
            ulonglong2 a = *(const ulonglong2*)sr;
            xp[0] = a.x; xp[1] = a.y;
        } else {
            xp[0] = *(const u64*)sr;
        }
        u64 wd[GPT];
#pragma unroll
        for (int i = 0; i < GPT; i++) wd[i] = pack2(wv[i], wv[i]);
#pragma unroll
        for (int i = 0; i < GPT; i++)
#pragma unroll
            for (int j = 0; j < NBP; j++)
                acc[i][j] = fma2(xp[j], wd[i], acc[i][j]);
    }
}

// ======================= PHASE A =======================
extern __shared__ float smemA[];
__global__ __launch_bounds__(NTA) void lstm_phaseA(
    const float* __restrict__ x,
    const float* __restrict__ w_ih1,
    const float* __restrict__ b_ih1,
    const float* __restrict__ b_hh1) {
    float* WS = smemA;                      // [128k][132]
    float* XT = smemA + DIN * WS_STRIDE;    // [128k][68]
    const int tid = threadIdx.x;
    const int wrp = tid >> 5, ln = tid & 31;
    const int cta = blockIdx.y;
    const int tg  = blockIdx.x;
    const int b0  = cta * BT;

    // stage W transposed: w_ih1[g][k] -> WS[k][g]
    for (int idx = tid; idx < G1 * DIN; idx += NTA) {
        int g = idx / DIN, k = idx % DIN;
        WS[k * WS_STRIDE + g] = w_ih1[idx];
    }
    // thread tile: 8 gates x 4 batch (2 batch-pairs); 16 ggrp x 16 bgrp = 256
    const int g0 = (tid >> 4) * 8;
    const int b0l = (tid & 15) * 4;
    u64 bd[8];
#pragma unroll
    for (int i = 0; i < 8; i++) {
        float bv = b_ih1[g0 + i] + b_hh1[g0 + i];
        bd[i] = pack2(bv, bv);
    }
    __syncthreads();

    for (int tt = 0; tt < TPB; tt++) {
        const int t = tg * TPB + tt;
        // stage x tile transposed: warp handles rows [wrp*8, wrp*8+8)
        for (int r = 0; r < 8; r++) {
            int bl = wrp * 8 + r;
            const float* xrow = x + ((size_t)(b0 + bl) * TT + t) * DIN;
#pragma unroll
            for (int i = 0; i < 4; i++)
                XT[(i * 32 + ln) * XT_STRIDE + bl] = xrow[i * 32 + ln];
        }
        __syncthreads();

        u64 acc[8][2];
#pragma unroll
        for (int i = 0; i < 8; i++) { acc[i][0] = bd[i]; acc[i][1] = bd[i]; }

        accum<WS_STRIDE, XT_STRIDE, 8, 2, DIN>(WS, XT, acc, g0, b0l);

        float* xgout = g_xg + ((size_t)(cta * TT + t) * G1) * BT;
#pragma unroll
        for (int i = 0; i < 8; i++) {
            ulonglong2 v;
            v.x = acc[i][0]; v.y = acc[i][1];
            *(ulonglong2*)(xgout + (g0 + i) * BT + b0l) = v;
        }
        __syncthreads();   // before restaging XT
    }
}

// ======================= PHASE B =======================
template <int GPT>
__device__ __forceinline__ void store_gates2(float* __restrict__ GS,
                                             u64 (&acc)[GPT][2],
                                             int g0, int b0l) {
#pragma unroll
    for (int i = 0; i < GPT; i++) {
        ulonglong2 v;
        v.x = acc[i][0]; v.y = acc[i][1];
        *(ulonglong2*)(GS + (g0 + i) * BT + b0l) = v;
    }
}

template <int H>
__device__ __forceinline__ void ew(const float* __restrict__ GS,
                                   float* __restrict__ HS,
                                   float* __restrict__ CS,
                                   int jq, int bl) {
    constexpr int PJ = (H * BT) / NTB;   // H/8
#pragma unroll
    for (int jj = 0; jj < PJ; jj++) {
        int j = jq * PJ + jj;
        float iv = sigf(GS[j * BT + bl]);
        float fv = sigf(GS[(H + j) * BT + bl]);
        float gv = tanhf_(GS[(2 * H + j) * BT + bl]);
        float ov = sigf(GS[(3 * H + j) * BT + bl]);
        float c = fv * CS[j * BT + bl] + iv * gv;
        CS[j * BT + bl] = c;
        HS[j * BT + bl] = ov * tanhf_(c);
    }
}

extern __shared__ float smemB[];
__global__ __launch_bounds__(NTB, 1) void lstm_phaseB(
    const float* __restrict__ w_hh1,
    const float* __restrict__ w_ih2, const float* __restrict__ w_hh2,
    const float* __restrict__ b_ih2, const float* __restrict__ b_hh2,
    const float* __restrict__ w_ih3, const float* __restrict__ w_hh3,
    const float* __restrict__ b_ih3, const float* __restrict__ b_hh3,
    const float* __restrict__ fc_w, const float* __restrict__ fc_b,
    float* __restrict__ out) {
    const int tid = threadIdx.x;
    const int cta = blockIdx.x;

    float* W1H = smemB + OFF_W1H;
    float* W2X = smemB + OFF_W2X;
    float* W2H = smemB + OFF_W2H;
    float* B2  = smemB + OFF_B2;
    float* W3X = smemB + OFF_W3X;
    float* W3H = smemB + OFF_W3H;
    float* B3  = smemB + OFF_B3;
    float* GS  = smemB + OFF_GS;
    float* H1S = smemB + OFF_H1S;
    float* C1S = smemB + OFF_C1S;
    float* H2S = smemB + OFF_H2S;
    float* C2S = smemB + OFF_C2S;
    float* H3S = smemB + OFF_H3S;
    float* C3S = smemB + OFF_C3S;

    // stage weights transposed [k][g]
    for (int i = tid; i < G1 * H1; i += NTB) { int g = i / H1, k = i % H1; W1H[k * G1 + g] = w_hh1[i]; }
    for (int i = tid; i < G2 * H1; i += NTB) { int g = i / H1, k = i % H1; W2X[k * G2 + g] = w_ih2[i]; }
    for (int i = tid; i < G2 * H2; i += NTB) { int g = i / H2, k = i % H2; W2H[k * G2 + g] = w_hh2[i]; }
    for (int i = tid; i < G2;      i += NTB) { B2[i] = b_ih2[i] + b_hh2[i]; }
    for (int i = tid; i < G3 * H2; i += NTB) { int g = i / H2, k = i % H2; W3X[k * G3 + g] = w_ih3[i]; }
    for (int i = tid; i < G3 * H3; i += NTB) { int g = i / H3, k = i % H3; W3H[k * G3 + g] = w_hh3[i]; }
    for (int i = tid; i < G3;      i += NTB) { B3[i] = b_ih3[i] + b_hh3[i]; }
    for (int i = tid; i < H1 * BT; i += NTB) { H1S[i] = 0.f; C1S[i] = 0.f; }
    for (int i = tid; i < H2 * BT; i += NTB) { H2S[i] = 0.f; C2S[i] = 0.f; }
    for (int i = tid; i < H3 * BT; i += NTB) { H3S[i] = 0.f; C3S[i] = 0.f; }

    // layer-1 mapping (tid < 256): 8 gates x 4 batch per thread
    const int g0l1 = (tid >> 4) * 8;      // 0..120 (for tid<256)
    const int b0l1 = (tid & 15) * 4;
    // layer-2 mapping (tid < 128): 8 gates x 4 batch
    const int g0l2 = (tid >> 4) * 8;      // 0..56
    const int b0l2 = (tid & 15) * 4;
    // layer-3 mapping (tid < 128): 4 gates x 4 batch
    const int g0l3 = (tid >> 4) * 4;      // 0..28
    const int b0l3 = (tid & 15) * 4;
    // ew mapping (all 512)
    const int jq = tid >> 6;              // 0..7
    const int bl = tid & 63;

    const float* xgbase = g_xg + (size_t)cta * TT * G1 * BT;

    // prefetch XG(t=0) into registers (8 gates x 1 ulonglong2 each)
    ulonglong2 xga[8];
    if (tid < 256) {
#pragma unroll
        for (int i = 0; i < 8; i++)
            xga[i] = *(const ulonglong2*)(xgbase + (size_t)(g0l1 + i) * BT + b0l1);
    }

    __syncthreads();

    for (int t = 0; t < TT; ++t) {
        // ---- layer 1 gates: acc init from XG, += h1 @ W1H ----
        if (tid < 256) {
            u64 acc[8][2];
#pragma unroll
            for (int i = 0; i < 8; i++) { acc[i][0] = xga[i].x; acc[i][1] = xga[i].y; }
            accum<G1, BT, 8, 2, H1>(W1H, H1S, acc, g0l1, b0l1);
            store_gates2<8>(GS, acc, g0l1, b0l1);
            // prefetch next timestep's XG (full timestep of latency cover)
            if (t + 1 < TT) {
#pragma unroll
                for (int i = 0; i < 8; i++)
                    xga[i] = *(const ulonglong2*)(xgbase + (size_t)((t + 1) * G1 + g0l1 + i) * BT + b0l1);
            }
        }
        __syncthreads();
        ew<H1>(GS, H1S, C1S, jq, bl);
        __syncthreads();

        // ---- layer 2 ----
        if (tid < 128) {
            u64 acc[8][2];
#pragma unroll
            for (int i = 0; i < 8; i++) {
                float bv = B2[g0l2 + i];
                acc[i][0] = pack2(bv, bv);
                acc[i][1] = acc[i][0];
            }
            accum<G2, BT, 8, 2, H1>(W2X, H1S, acc, g0l2, b0l2);
            accum<G2, BT, 8, 2, H2>(W2H, H2S, acc, g0l2, b0l2);
            store_gates2<8>(GS, acc, g0l2, b0l2);
        }
        __syncthreads();
        ew<H2>(GS, H2S, C2S, jq, bl);
        __syncthreads();

        // ---- layer 3 ----
        if (tid < 128) {
            u64 acc[4][2];
#pragma unroll
            for (int i = 0; i < 4; i++) {
                float bv = B3[g0l3 + i];
                acc[i][0] = pack2(bv, bv);
                acc[i][1] = acc[i][0];
            }
            accum<G3, BT, 4, 2, H2>(W3X, H2S, acc, g0l3, b0l3);
            accum<G3, BT, 4, 2, H3>(W3H, H3S, acc, g0l3, b0l3);
            store_gates2<4>(GS, acc, g0l3, b0l3);
        }
        __syncthreads();
        ew<H3>(GS, H3S, C3S, jq, bl);
        __syncthreads();
    }

    // final FC
    if (tid < BT) {
        float acc = fc_b[0];
#pragma unroll
        for (int j = 0; j < H3; j++) acc += fc_w[j] * H3S[j * BT + tid];
        out[cta * BT + tid] = acc;
    }
}

extern "C" void kernel_launch(void* const* d_in, const int* in_sizes, int n_in,
                              void* d_out, int out_size) {
    (void)in_sizes; (void)n_in; (void)out_size;
    const float* x     = (const float*)d_in[0];
    const float* w_ih1 = (const float*)d_in[1];
    const float* w_hh1 = (const float*)d_in[2];
    const float* b_ih1 = (const float*)d_in[3];
    const float* b_hh1 = (const float*)d_in[4];
    const float* w_ih2 = (const float*)d_in[5];
    const float* w_hh2 = (const float*)d_in[6];
    const float* b_ih2 = (const float*)d_in[7];
    const float* b_hh2 = (const float*)d_in[8];
    const float* w_ih3 = (const float*)d_in[9];
    const float* w_hh3 = (const float*)d_in[10];
    const float* b_ih3 = (const float*)d_in[11];
    const float* b_hh3 = (const float*)d_in[12];
    const float* fc_w  = (const float*)d_in[13];
    const float* fc_b  = (const float*)d_in[14];
    float* out = (float*)d_out;

    cudaFuncSetAttribute(lstm_phaseA,
                         cudaFuncAttributeMaxDynamicSharedMemorySize, A_SMEM_BYTES);
    cudaFuncSetAttribute(lstm_phaseB,
                         cudaFuncAttributeMaxDynamicSharedMemorySize, B_SMEM_BYTES);

    dim3 gridA(TT / TPB, NCTA);
    lstm_phaseA<<<gridA, NTA, A_SMEM_BYTES>>>(x, w_ih1, b_ih1, b_hh1);
    lstm_phaseB<<<NCTA, NTB, B_SMEM_BYTES>>>(
        w_hh1, w_ih2, w_hh2, b_ih2, b_hh2,
        w_ih3, w_hh3, b_ih3, b_hh3, fc_w, fc_b, out);
}